// round 11
// baseline (speedup 1.0000x reference)
#include <cuda_runtime.h>

// ============================================================================
// GeneratorQuantumCircuit: 4-qubit state-vector sim, 1 thread = 1 batch elem.
// State = 16 complex amplitudes packed (re,im) as f32x2 in 64-bit registers.
//
// R10: deferred-cosine gate algebra. Every rotation gate is applied as the
// unit-diagonal matrix [[1,-t],[t,1]] (t = tan(theta/2-ish)), and the cosine
// factors are accumulated into a single scalar K applied once to the final
// probabilities (as K^2). Halves the RY fma count (2 fma2/pair) and the RX
// build (1 mul2/pair). Epilogue (squares + marginals) done in packed f32x2.
// ============================================================================

typedef unsigned long long u64;

__device__ float g_wt[8];   // tan(weights[l][w] * 0.5)
__device__ float g_kw;      // prod_l,w cos(weights[l][w] * 0.5)

__global__ void prep_weights_kernel(const float* __restrict__ w) {
    if (threadIdx.x == 0) {
        double prod = 1.0;
        for (int i = 0; i < 8; i++) {
            double th = 0.5 * (double)w[i];
            double c = cos(th), s = sin(th);
            g_wt[i] = (float)(s / c);
            prod *= c;
        }
        g_kw = (float)prod;
    }
}

// ---- packed f32x2 helpers (Blackwell sm_100+) ------------------------------

__device__ __forceinline__ u64 pk2(float lo, float hi) {
    u64 r; asm("mov.b64 %0, {%1, %2};" : "=l"(r) : "f"(lo), "f"(hi)); return r;
}
__device__ __forceinline__ void unpk2(u64 v, float& lo, float& hi) {
    asm("mov.b64 {%0, %1}, %2;" : "=f"(lo), "=f"(hi) : "l"(v));
}
__device__ __forceinline__ u64 mul2(u64 a, u64 b) {
    u64 r; asm("mul.rn.f32x2 %0, %1, %2;" : "=l"(r) : "l"(a), "l"(b)); return r;
}
__device__ __forceinline__ u64 add2(u64 a, u64 b) {
    u64 r; asm("add.rn.f32x2 %0, %1, %2;" : "=l"(r) : "l"(a), "l"(b)); return r;
}
__device__ __forceinline__ u64 fma2(u64 a, u64 b, u64 c) {
    u64 r; asm("fma.rn.f32x2 %0, %1, %2, %3;" : "=l"(r) : "l"(a), "l"(b), "l"(c)); return r;
}
__device__ __forceinline__ float hadd2(u64 v) {
    float lo, hi; unpk2(v, lo, hi); return lo + hi;
}

// CNOT(ctrl C, tgt T): pure register permutation when fully unrolled.
template <int C, int T>
__device__ __forceinline__ void cnot(u64* a) {
#pragma unroll
    for (int i = 0; i < 16; i++) {
        if ((i & (1 << C)) && !(i & (1 << T))) {
            u64 t = a[i];
            a[i] = a[i | (1 << T)];
            a[i | (1 << T)] = t;
        }
    }
}

__global__ void __launch_bounds__(256)
qc_kernel(const float4* __restrict__ noise, float4* __restrict__ out, int n) {
    int b = blockIdx.x * blockDim.x + threadIdx.x;
    if (b >= n) return;

    // ---- batch-uniform weight tangents + cosine product (L1 broadcast) -----
    float wt[8];
#pragma unroll
    for (int i = 0; i < 8; i++) wt[i] = g_wt[i];
    float kw = g_kw;

    // ---- noise angles -> cos/sin -> tangents; accumulate cosine product ----
    float4 nz = noise[b];
    float c[4], s[4], t[4];
    __sincosf(0.5f * nz.x, &s[0], &c[0]);
    __sincosf(0.5f * nz.y, &s[1], &c[1]);
    __sincosf(0.5f * nz.z, &s[2], &c[2]);
    __sincosf(0.5f * nz.w, &s[3], &c[3]);
#pragma unroll
    for (int w = 0; w < 4; w++) t[w] = __fdividef(s[w], c[w]);

    float K  = ((c[0] * c[1]) * (c[2] * c[3])) * kw;  // all deferred cosines
    float K2 = K * K;                                 // probability scale

    // ---- product state with deferred cosines: amp(i) = prod_w (i_w?-i*t:1) -
    // a[i] packed (re,im). a[i+h] = a[i] * (-i t) = (im*t, -re*t).
    u64 a[16];
    a[0] = pk2(1.0f, 0.0f);
#pragma unroll
    for (int w = 0; w < 4; w++) {
        const int h = 1 << w;
        u64 tn = pk2(t[w], -t[w]);
#pragma unroll
        for (int i = 0; i < (1 << w); i++) {
            float re, im;
            unpk2(a[i], re, im);
            a[i + h] = mul2(pk2(im, re), tn);
        }
    }

    // ---- 2 layers: CNOT ring + RY (deferred cosine: [[1,-t],[t,1]]) --------
#pragma unroll
    for (int layer = 0; layer < 2; layer++) {
        cnot<0, 1>(a);
        cnot<1, 2>(a);
        cnot<2, 3>(a);
        cnot<3, 0>(a);

#pragma unroll
        for (int w = 0; w < 4; w++) {
            float tw = wt[layer * 4 + w];
            u64 tp = pk2(tw, tw);
            u64 tn = pk2(-tw, -tw);
            const int h = 1 << w;
#pragma unroll
            for (int i = 0; i < 16; i++) {
                if (i & h) continue;
                u64 a0 = a[i], a1 = a[i | h];
                a[i]     = fma2(tn, a1, a0);  // a0 - t*a1  (re & im together)
                a[i | h] = fma2(tp, a0, a1);  // a1 + t*a0
            }
        }
    }

    // ---- packed squares + marginals: out_w = K^2 * sum_{bit w==0} |a_i|^2 --
    u64 q[16];
#pragma unroll
    for (int i = 0; i < 16; i++) q[i] = mul2(a[i], a[i]);  // (re^2, im^2)

    u64 s01 = add2(q[0],  q[1]),  s23 = add2(q[2],  q[3]);
    u64 s45 = add2(q[4],  q[5]),  s67 = add2(q[6],  q[7]);
    u64 s89 = add2(q[8],  q[9]),  sab = add2(q[10], q[11]);
    u64 scd = add2(q[12], q[13]);

    u64 A = add2(s01, s23);   // q0..q3
    u64 B = add2(s45, s67);   // q4..q7
    u64 C = add2(s89, sab);   // q8..q11

    // wire0: even indices
    u64 E = add2(add2(add2(q[0], q[2]), add2(q[4],  q[6])),
                 add2(add2(q[8], q[10]), add2(q[12], q[14])));
    // wire1: {0,1,4,5,8,9,12,13}
    u64 Y = add2(add2(s01, s45), add2(s89, scd));

    float4 o;
    o.x = K2 * hadd2(E);             // wire 0
    o.y = K2 * hadd2(Y);             // wire 1
    o.z = K2 * hadd2(add2(A, C));    // wire 2
    o.w = K2 * hadd2(add2(A, B));    // wire 3

    out[b] = o;
}

extern "C" void kernel_launch(void* const* d_in, const int* in_sizes, int n_in,
                              void* d_out, int out_size) {
    const float* noise   = (const float*)d_in[0];   // (B, 4) f32
    const float* weights = (const float*)d_in[1];   // (2, 4) f32
    int B = in_sizes[0] / 4;

    prep_weights_kernel<<<1, 32>>>(weights);

    int threads = 256;
    int blocks = (B + threads - 1) / threads;
    qc_kernel<<<blocks, threads>>>((const float4*)noise, (float4*)d_out, B);
}

// round 12
// speedup vs baseline: 1.6277x; 1.6277x over previous
#include <cuda_runtime.h>

// ============================================================================
// GeneratorQuantumCircuit: 4-qubit state-vector sim, 1 thread = 1 batch elem.
// State = 16 complex amplitudes packed (re,im) as f32x2 in 64-bit registers.
//
// Tangent (deferred-cosine) gate algebra: every rotation applied as
// [[1,-t],[t,1]]; the dropped cosine factors are recovered at the end by
// SELF-NORMALIZATION (circuit is unitary => sum of probs = 1), so no cosine
// product is ever computed. RY gates: 2 fma2 per amplitude pair. CNOTs:
// register renames. Epilogue in packed f32x2 + one MUFU reciprocal.
// R11: prep kernel back to parallel fp32 (R10's serial fp64 prep cost ~13us).
// ============================================================================

typedef unsigned long long u64;

__device__ float g_wt[8];   // tan(weights[l][w] * 0.5)

__global__ void prep_weights_kernel(const float* __restrict__ w) {
    int i = threadIdx.x;
    if (i < 8) g_wt[i] = tanf(0.5f * w[i]);   // accurate fp32 tan, 8 par threads
}

// ---- packed f32x2 helpers (Blackwell sm_100+) ------------------------------

__device__ __forceinline__ u64 pk2(float lo, float hi) {
    u64 r; asm("mov.b64 %0, {%1, %2};" : "=l"(r) : "f"(lo), "f"(hi)); return r;
}
__device__ __forceinline__ void unpk2(u64 v, float& lo, float& hi) {
    asm("mov.b64 {%0, %1}, %2;" : "=f"(lo), "=f"(hi) : "l"(v));
}
__device__ __forceinline__ u64 mul2(u64 a, u64 b) {
    u64 r; asm("mul.rn.f32x2 %0, %1, %2;" : "=l"(r) : "l"(a), "l"(b)); return r;
}
__device__ __forceinline__ u64 add2(u64 a, u64 b) {
    u64 r; asm("add.rn.f32x2 %0, %1, %2;" : "=l"(r) : "l"(a), "l"(b)); return r;
}
__device__ __forceinline__ u64 fma2(u64 a, u64 b, u64 c) {
    u64 r; asm("fma.rn.f32x2 %0, %1, %2, %3;" : "=l"(r) : "l"(a), "l"(b), "l"(c)); return r;
}
__device__ __forceinline__ float hadd2(u64 v) {
    float lo, hi; unpk2(v, lo, hi); return lo + hi;
}

// CNOT(ctrl C, tgt T): pure register permutation when fully unrolled.
template <int C, int T>
__device__ __forceinline__ void cnot(u64* a) {
#pragma unroll
    for (int i = 0; i < 16; i++) {
        if ((i & (1 << C)) && !(i & (1 << T))) {
            u64 t = a[i];
            a[i] = a[i | (1 << T)];
            a[i | (1 << T)] = t;
        }
    }
}

__global__ void __launch_bounds__(256)
qc_kernel(const float4* __restrict__ noise, float4* __restrict__ out, int n) {
    int b = blockIdx.x * blockDim.x + threadIdx.x;
    if (b >= n) return;

    // ---- batch-uniform weight tangents (L1 broadcast) -----------------------
    float wt[8];
#pragma unroll
    for (int i = 0; i < 8; i++) wt[i] = g_wt[i];

    // ---- noise angles -> tangents (cosines never needed: self-normalizing) -
    float4 nz = noise[b];
    float c[4], s[4], t[4];
    __sincosf(0.5f * nz.x, &s[0], &c[0]);
    __sincosf(0.5f * nz.y, &s[1], &c[1]);
    __sincosf(0.5f * nz.z, &s[2], &c[2]);
    __sincosf(0.5f * nz.w, &s[3], &c[3]);
#pragma unroll
    for (int w = 0; w < 4; w++) t[w] = __fdividef(s[w], c[w]);

    // ---- product state (deferred cosines): amp(i) = prod_w (i_w ? -i*t : 1)
    // a[i] packed (re,im). a[i+h] = a[i] * (-i t) = (im*t, -re*t).
    u64 a[16];
    a[0] = pk2(1.0f, 0.0f);
#pragma unroll
    for (int w = 0; w < 4; w++) {
        const int h = 1 << w;
        u64 tn = pk2(t[w], -t[w]);
#pragma unroll
        for (int i = 0; i < (1 << w); i++) {
            float re, im;
            unpk2(a[i], re, im);
            a[i + h] = mul2(pk2(im, re), tn);
        }
    }

    // ---- 2 layers: CNOT ring + RY (deferred cosine: [[1,-t],[t,1]]) --------
#pragma unroll
    for (int layer = 0; layer < 2; layer++) {
        cnot<0, 1>(a);
        cnot<1, 2>(a);
        cnot<2, 3>(a);
        cnot<3, 0>(a);

#pragma unroll
        for (int w = 0; w < 4; w++) {
            float tw = wt[layer * 4 + w];
            u64 tp = pk2(tw, tw);
            u64 tn = pk2(-tw, -tw);
            const int h = 1 << w;
#pragma unroll
            for (int i = 0; i < 16; i++) {
                if (i & h) continue;
                u64 a0 = a[i], a1 = a[i | h];
                a[i]     = fma2(tn, a1, a0);  // a0 - t*a1  (re & im together)
                a[i | h] = fma2(tp, a0, a1);  // a1 + t*a0
            }
        }
    }

    // ---- packed squares + marginals, then normalize by total ---------------
    u64 q[16];
#pragma unroll
    for (int i = 0; i < 16; i++) q[i] = mul2(a[i], a[i]);  // (re^2, im^2)

    u64 s01 = add2(q[0],  q[1]),  s23 = add2(q[2],  q[3]);
    u64 s45 = add2(q[4],  q[5]),  s67 = add2(q[6],  q[7]);
    u64 s89 = add2(q[8],  q[9]),  sab = add2(q[10], q[11]);
    u64 scd = add2(q[12], q[13]), sef = add2(q[14], q[15]);

    u64 A = add2(s01, s23);   // q0..q3
    u64 B = add2(s45, s67);   // q4..q7
    u64 C = add2(s89, sab);   // q8..q11
    u64 D = add2(scd, sef);   // q12..q15

    // wire0: even indices
    u64 E = add2(add2(add2(q[0], q[2]), add2(q[4],  q[6])),
                 add2(add2(q[8], q[10]), add2(q[12], q[14])));
    // wire1: {0,1,4,5,8,9,12,13}
    u64 Y = add2(add2(s01, s45), add2(s89, scd));

    u64 AB = add2(A, B);                    // wire 3 numerator (and half of T)
    float T = hadd2(add2(AB, add2(C, D)));  // total probability mass
    float r = __frcp_rn(T);                 // MUFU reciprocal (pipe is idle)

    float4 o;
    o.x = r * hadd2(E);            // wire 0
    o.y = r * hadd2(Y);            // wire 1
    o.z = r * hadd2(add2(A, C));   // wire 2
    o.w = r * hadd2(AB);           // wire 3

    out[b] = o;
}

extern "C" void kernel_launch(void* const* d_in, const int* in_sizes, int n_in,
                              void* d_out, int out_size) {
    const float* noise   = (const float*)d_in[0];   // (B, 4) f32
    const float* weights = (const float*)d_in[1];   // (2, 4) f32
    int B = in_sizes[0] / 4;

    prep_weights_kernel<<<1, 32>>>(weights);

    int threads = 256;
    int blocks = (B + threads - 1) / threads;
    qc_kernel<<<blocks, threads>>>((const float4*)noise, (float4*)d_out, B);
}

// round 13
// speedup vs baseline: 1.6497x; 1.0135x over previous
#include <cuda_runtime.h>

// ============================================================================
// GeneratorQuantumCircuit: 4-qubit state-vector sim, 1 thread = 1 batch elem.
// State = 16 complex amplitudes packed (re,im) as f32x2 in 64-bit registers.
//
// Tangent (deferred-cosine) gate algebra: every rotation applied as
// [[1,-t],[t,1]]; dropped cosine factors recovered by SELF-NORMALIZATION
// (unitary circuit => sum of probs = 1). RY gates: 2 fma2 per amplitude pair.
// CNOTs: register renames. Epilogue in packed f32x2 + one MUFU reciprocal.
//
// R12: single-kernel design. Weight tangents computed per block (threads 0-7,
// tanf into smem + one barrier) instead of a separate prep launch, which was
// costing ~2.8us of serialized launch overhead in the graph.
// ============================================================================

typedef unsigned long long u64;

// ---- packed f32x2 helpers (Blackwell sm_100+) ------------------------------

__device__ __forceinline__ u64 pk2(float lo, float hi) {
    u64 r; asm("mov.b64 %0, {%1, %2};" : "=l"(r) : "f"(lo), "f"(hi)); return r;
}
__device__ __forceinline__ void unpk2(u64 v, float& lo, float& hi) {
    asm("mov.b64 {%0, %1}, %2;" : "=f"(lo), "=f"(hi) : "l"(v));
}
__device__ __forceinline__ u64 mul2(u64 a, u64 b) {
    u64 r; asm("mul.rn.f32x2 %0, %1, %2;" : "=l"(r) : "l"(a), "l"(b)); return r;
}
__device__ __forceinline__ u64 add2(u64 a, u64 b) {
    u64 r; asm("add.rn.f32x2 %0, %1, %2;" : "=l"(r) : "l"(a), "l"(b)); return r;
}
__device__ __forceinline__ u64 fma2(u64 a, u64 b, u64 c) {
    u64 r; asm("fma.rn.f32x2 %0, %1, %2, %3;" : "=l"(r) : "l"(a), "l"(b), "l"(c)); return r;
}
__device__ __forceinline__ float hadd2(u64 v) {
    float lo, hi; unpk2(v, lo, hi); return lo + hi;
}

// CNOT(ctrl C, tgt T): pure register permutation when fully unrolled.
template <int C, int T>
__device__ __forceinline__ void cnot(u64* a) {
#pragma unroll
    for (int i = 0; i < 16; i++) {
        if ((i & (1 << C)) && !(i & (1 << T))) {
            u64 t = a[i];
            a[i] = a[i | (1 << T)];
            a[i | (1 << T)] = t;
        }
    }
}

__global__ void __launch_bounds__(256)
qc_kernel(const float4* __restrict__ noise,
          const float*  __restrict__ weights,
          float4* __restrict__ out, int n) {
    __shared__ float wt_sh[8];

    // ---- per-block weight tangents: 8 accurate tanf, once per block --------
    if (threadIdx.x < 8) wt_sh[threadIdx.x] = tanf(0.5f * weights[threadIdx.x]);
    __syncthreads();

    int b = blockIdx.x * blockDim.x + threadIdx.x;
    if (b >= n) return;

    float wt[8];
#pragma unroll
    for (int i = 0; i < 8; i++) wt[i] = wt_sh[i];   // LDS broadcast, N=1

    // ---- noise angles -> tangents (cosines never needed: self-normalizing) -
    float4 nz = noise[b];
    float c[4], s[4], t[4];
    __sincosf(0.5f * nz.x, &s[0], &c[0]);
    __sincosf(0.5f * nz.y, &s[1], &c[1]);
    __sincosf(0.5f * nz.z, &s[2], &c[2]);
    __sincosf(0.5f * nz.w, &s[3], &c[3]);
#pragma unroll
    for (int w = 0; w < 4; w++) t[w] = __fdividef(s[w], c[w]);

    // ---- product state (deferred cosines): amp(i) = prod_w (i_w ? -i*t : 1)
    // a[i] packed (re,im). a[i+h] = a[i] * (-i t) = (im*t, -re*t).
    u64 a[16];
    a[0] = pk2(1.0f, 0.0f);
#pragma unroll
    for (int w = 0; w < 4; w++) {
        const int h = 1 << w;
        u64 tn = pk2(t[w], -t[w]);
#pragma unroll
        for (int i = 0; i < (1 << w); i++) {
            float re, im;
            unpk2(a[i], re, im);
            a[i + h] = mul2(pk2(im, re), tn);
        }
    }

    // ---- 2 layers: CNOT ring + RY (deferred cosine: [[1,-t],[t,1]]) --------
#pragma unroll
    for (int layer = 0; layer < 2; layer++) {
        cnot<0, 1>(a);
        cnot<1, 2>(a);
        cnot<2, 3>(a);
        cnot<3, 0>(a);

#pragma unroll
        for (int w = 0; w < 4; w++) {
            float tw = wt[layer * 4 + w];
            u64 tp = pk2(tw, tw);
            u64 tn = pk2(-tw, -tw);
            const int h = 1 << w;
#pragma unroll
            for (int i = 0; i < 16; i++) {
                if (i & h) continue;
                u64 a0 = a[i], a1 = a[i | h];
                a[i]     = fma2(tn, a1, a0);  // a0 - t*a1  (re & im together)
                a[i | h] = fma2(tp, a0, a1);  // a1 + t*a0
            }
        }
    }

    // ---- packed squares + marginals, then normalize by total ---------------
    u64 q[16];
#pragma unroll
    for (int i = 0; i < 16; i++) q[i] = mul2(a[i], a[i]);  // (re^2, im^2)

    u64 s01 = add2(q[0],  q[1]),  s23 = add2(q[2],  q[3]);
    u64 s45 = add2(q[4],  q[5]),  s67 = add2(q[6],  q[7]);
    u64 s89 = add2(q[8],  q[9]),  sab = add2(q[10], q[11]);
    u64 scd = add2(q[12], q[13]), sef = add2(q[14], q[15]);

    u64 A = add2(s01, s23);   // q0..q3
    u64 B = add2(s45, s67);   // q4..q7
    u64 C = add2(s89, sab);   // q8..q11
    u64 D = add2(scd, sef);   // q12..q15

    // wire0: even indices
    u64 E = add2(add2(add2(q[0], q[2]), add2(q[4],  q[6])),
                 add2(add2(q[8], q[10]), add2(q[12], q[14])));
    // wire1: {0,1,4,5,8,9,12,13}
    u64 Y = add2(add2(s01, s45), add2(s89, scd));

    u64 AB = add2(A, B);                    // wire 3 numerator (and half of T)
    float T = hadd2(add2(AB, add2(C, D)));  // total probability mass
    float r = __frcp_rn(T);                 // MUFU reciprocal (pipe is idle)

    float4 o;
    o.x = r * hadd2(E);            // wire 0
    o.y = r * hadd2(Y);            // wire 1
    o.z = r * hadd2(add2(A, C));   // wire 2
    o.w = r * hadd2(AB);           // wire 3

    out[b] = o;
}

extern "C" void kernel_launch(void* const* d_in, const int* in_sizes, int n_in,
                              void* d_out, int out_size) {
    const float* noise   = (const float*)d_in[0];   // (B, 4) f32
    const float* weights = (const float*)d_in[1];   // (2, 4) f32
    int B = in_sizes[0] / 4;

    int threads = 256;
    int blocks = (B + threads - 1) / threads;
    qc_kernel<<<blocks, threads>>>((const float4*)noise, weights,
                                   (float4*)d_out, B);
}